// round 16
// baseline (speedup 1.0000x reference)
#include <cuda_runtime.h>
#include <cstdint>

// ---------------- problem constants ----------------
#define C_CH    321
#define D_K     512
#define P_OUT   720
#define N_B     64           // batch == GEMM M
#define BN      128          // p-tile == GEMM N
#define BK      32           // k-chunk
#define KCHUNKS (D_K / BK)   // 16
#define STAGES  3
#define NTHREADS 256

// ---------------- smem layout (A only; B goes global->register) ----------------
// A: 64 rows x 32 floats (128B rows), XOR-16B swizzle (ldmatrix-ready, conflict-free).
#define A_STAGE_BYTES  8192
#define SMEM_BYTES     (STAGES * A_STAGE_BYTES)   // 24576

// ---------------- helpers ----------------
__device__ __forceinline__ uint32_t smem_to_u32(const void* p) {
    uint32_t a;
    asm("{ .reg .u64 t; cvta.to.shared.u64 t, %1; cvt.u32.u64 %0, t; }" : "=r"(a) : "l"(p));
    return a;
}
// fp32 -> tf32 round-to-nearest via mantissa carry add (HMMA reads top 19 bits).
__device__ __forceinline__ uint32_t rtf32(float f) {
    return __float_as_uint(f) + 0x1000u;
}
#define CP_ASYNC16(dst, src) \
    asm volatile("cp.async.cg.shared.global [%0], [%1], 16;" :: "r"(dst), "l"(src))
#define CP_COMMIT()  asm volatile("cp.async.commit_group;" ::: "memory")
#define CP_WAIT1()   asm volatile("cp.async.wait_group 1;" ::: "memory")
#define LDMATRIX_X4(r0, r1, r2, r3, addr) \
    asm volatile("ldmatrix.sync.aligned.m8n8.x4.shared.b16 {%0,%1,%2,%3}, [%4];" \
        : "=r"(r0), "=r"(r1), "=r"(r2), "=r"(r3) : "r"(addr))

__device__ __forceinline__ void mma_tf32(float* acc, const uint32_t* a, const uint32_t* b) {
    asm volatile(
        "mma.sync.aligned.m16n8k8.row.col.f32.tf32.tf32.f32 "
        "{%0,%1,%2,%3}, {%4,%5,%6,%7}, {%8,%9}, {%0,%1,%2,%3};"
        : "+f"(acc[0]), "+f"(acc[1]), "+f"(acc[2]), "+f"(acc[3])
        : "r"(a[0]), "r"(a[1]), "r"(a[2]), "r"(a[3]), "r"(b[0]), "r"(b[1]));
}

// ---------------- kernel ----------------
// CTA (blockIdx.x = p-tile, blockIdx.y = channel c):
//   out[b, c, p0:p0+128] = x[b, c, :] @ W[c, :, p0:p0+128] + bias[c, p0:p0+128]
// M=64 x N=128 x K=512 tf32 mma.sync; 8 warps in 1x8 grid (warp tile 64x16).
// A via 3-stage cp.async + ldmatrix (x truncated to tf32).
// B fragments loaded DIRECTLY global->register (each W element is consumed by
// exactly one warp once): 16 __ldcs LDG.32/chunk/warp issued before the A-wait
// barrier; streaming hint keeps W from evicting x's L2 working set.
__global__ void __launch_bounds__(NTHREADS, 3)
pc_linear_mma(const float* __restrict__ x,
              const float* __restrict__ W,
              const float* __restrict__ bias,
              float* __restrict__ out)
{
    extern __shared__ float sm[];
    const uint32_t sbase = smem_to_u32(sm);

    const int tid  = threadIdx.x;
    const int lane = tid & 31;
    const int wid  = tid >> 5;    // warp col (0..7) -> n0 = wid*16
    const int gid  = lane >> 2;   // fragment group id (0..7)
    const int tig  = lane & 3;    // thread in group (0..3)
    const int c    = blockIdx.y;
    const int p0   = blockIdx.x * BN;

    const float* xc = x + (size_t)c * D_K;
    const float* Wc = W + (size_t)c * ((size_t)D_K * P_OUT);

    // ---- per-lane ldmatrix offsets (A tile; mt adds 2048B = 16 rows) ----
    // 128B rows, swizzle: 16B-chunk ^= (row & 7). Conflict-free (proven R9/R10).
    uint32_t foff[4];
    {
        const int m0  = (lane & 7) + (lane & 8);
        const int swz = (m0 & 7) * 16;
        const int hi  = (lane >> 4) * 16;
#pragma unroll
        for (int ks = 0; ks < 4; ++ks)
            foff[ks] = (uint32_t)(m0 * 128 + ((ks * 32 + hi) ^ swz));
    }

    // ---- B fragment pointers (advance by 32 k-rows per chunk) ----
    // lane supplies cols p0 + wid*16 + nt*8 + gid at rows tig (+4, +8*ks).
    const float* bp[2];
#pragma unroll
    for (int nt = 0; nt < 2; ++nt) {
        int p = p0 + wid * 16 + nt * 8 + gid;
        if (p >= P_OUT) p = P_OUT - 1;       // ragged tile: bounded dummy read
        bp[nt] = Wc + (size_t)tig * P_OUT + p;
    }

    // ---- cp.async issue for one A K-chunk into one stage ----
    auto issueA = [&](int chunk, int stage) {
        const int k0 = chunk * BK;
        const uint32_t abase = sbase + (uint32_t)stage * A_STAGE_BYTES;
#pragma unroll
        for (int i = 0; i < 2; ++i) {
            const int id   = tid + i * NTHREADS;
            const int r    = id >> 3;          // batch row
            const int col4 = (id & 7) * 4;     // k offset (16B chunk)
            const float* src = xc + (size_t)r * (C_CH * D_K) + k0 + col4;
            const uint32_t fo = (uint32_t)(r * 32 + (col4 ^ ((r & 7) * 4)));
            CP_ASYNC16(abase + fo * 4, src);
        }
    };

    float acc[4][2][4];   // mt x nt x quad (32 regs)
#pragma unroll
    for (int mt = 0; mt < 4; ++mt)
#pragma unroll
        for (int nt = 0; nt < 2; ++nt)
#pragma unroll
            for (int q = 0; q < 4; ++q) acc[mt][nt][q] = 0.f;

    // ---- prologue: 2 A chunks in flight ----
    issueA(0, 0); CP_COMMIT();
    issueA(1, 1); CP_COMMIT();

    // ---- mainloop ----
#pragma unroll 1
    for (int i = 0; i < KCHUNKS; ++i) {
        // 1) B fragment loads for chunk i (global, streaming) -- issued early,
        //    covered by the A-wait + barrier + A-issue + ldmatrix below.
        float braw[4][2][2];
#pragma unroll
        for (int ks = 0; ks < 4; ++ks)
#pragma unroll
            for (int nt = 0; nt < 2; ++nt) {
                braw[ks][nt][0] = __ldcs(bp[nt] + (size_t)(ks * 8) * P_OUT);
                braw[ks][nt][1] = __ldcs(bp[nt] + (size_t)(ks * 8 + 4) * P_OUT);
            }
        bp[0] += (size_t)BK * P_OUT;
        bp[1] += (size_t)BK * P_OUT;

        // 2) A pipeline
        CP_WAIT1();              // A chunk i landed
        __syncthreads();         // publish stage i; proves compute(i-1) done (WAR-safe)
        if (i + 2 < KCHUNKS) issueA(i + 2, (i + 2) % STAGES);
        CP_COMMIT();             // commit every iter keeps ledger exact

        // 3) compute chunk i
        const uint32_t As_b = sbase + (uint32_t)(i % STAGES) * A_STAGE_BYTES;
#pragma unroll
        for (int ks = 0; ks < 4; ++ks) {
            uint32_t af[4][4], bf[2][2];
            const uint32_t a0 = As_b + foff[ks];
#pragma unroll
            for (int mt = 0; mt < 4; ++mt)
                LDMATRIX_X4(af[mt][0], af[mt][1], af[mt][2], af[mt][3],
                            a0 + (uint32_t)mt * 2048);
#pragma unroll
            for (int nt = 0; nt < 2; ++nt) {
                bf[nt][0] = rtf32(braw[ks][nt][0]);
                bf[nt][1] = rtf32(braw[ks][nt][1]);
            }
#pragma unroll
            for (int mt = 0; mt < 4; ++mt)
#pragma unroll
                for (int nt = 0; nt < 2; ++nt)
                    mma_tf32(acc[mt][nt], af[mt], bf[nt]);
        }
    }

    // ---- epilogue: D[b][p] + bias[c][p] -> out[b][c][p] (streaming stores) ----
#pragma unroll
    for (int nt = 0; nt < 2; ++nt) {
        const int p = p0 + wid * 16 + nt * 8 + tig * 2;
        if (p < P_OUT) {
            const float2 bv = *(const float2*)(bias + (size_t)c * P_OUT + p);
#pragma unroll
            for (int mt = 0; mt < 4; ++mt) {
                const int b0r = mt * 16 + gid;
                const float* a = acc[mt][nt];
                float2 v0 = make_float2(a[0] + bv.x, a[1] + bv.y);
                float2 v1 = make_float2(a[2] + bv.x, a[3] + bv.y);
                __stcs((float2*)(out + ((size_t)b0r * C_CH + c) * P_OUT + p), v0);
                __stcs((float2*)(out + ((size_t)(b0r + 8) * C_CH + c) * P_OUT + p), v1);
            }
        }
    }
}

// ---------------- launch ----------------
extern "C" void kernel_launch(void* const* d_in, const int* in_sizes, int n_in,
                              void* d_out, int out_size) {
    const float* x  = (const float*)d_in[0];  // [64, 321, 512]
    const float* W  = (const float*)d_in[1];  // [321, 512, 720]
    const float* bi = (const float*)d_in[2];  // [321, 720]
    float* out      = (float*)d_out;          // [64, 321, 720]

    cudaFuncSetAttribute(pc_linear_mma,
                         cudaFuncAttributeMaxDynamicSharedMemorySize, SMEM_BYTES);
    dim3 grid((P_OUT + BN - 1) / BN, C_CH);   // 6 x 321 = 1926 CTAs
    pc_linear_mma<<<grid, NTHREADS, SMEM_BYTES>>>(x, W, bi, out);
}

// round 17
// speedup vs baseline: 1.0761x; 1.0761x over previous
#include <cuda_runtime.h>
#include <cstdint>

// ---------------- problem constants ----------------
#define C_CH    321
#define D_K     512
#define P_OUT   720
#define N_B     64           // batch == GEMM M
#define BN      128          // p-tile == GEMM N
#define BK      32           // k-chunk
#define KCHUNKS (D_K / BK)   // 16
#define STAGES  3
#define NTHREADS 256
#define NTILES  (6 * C_CH)   // 1926
#define NSLOTS  444          // 148 SMs x 3 CTAs

// ---------------- smem layout (identical to R10) ----------------
#define A_STAGE_BYTES  8192
#define B_STRIDE 136
#define B_STAGE_BYTES  (BK * B_STRIDE * 4)   // 17408
#define B_BASE         (STAGES * A_STAGE_BYTES)            // 24576
#define SMEM_BYTES     (B_BASE + STAGES * B_STAGE_BYTES)   // 76800 (75 KB) -> 3 CTAs/SM

// ---------------- helpers ----------------
__device__ __forceinline__ uint32_t smem_to_u32(const void* p) {
    uint32_t a;
    asm("{ .reg .u64 t; cvta.to.shared.u64 t, %1; cvt.u32.u64 %0, t; }" : "=r"(a) : "l"(p));
    return a;
}
// fp32 -> tf32 round-to-nearest via mantissa carry add (HMMA reads top 19 bits).
__device__ __forceinline__ uint32_t rtf32(float f) {
    return __float_as_uint(f) + 0x1000u;
}
#define CP_ASYNC16(dst, src) \
    asm volatile("cp.async.cg.shared.global [%0], [%1], 16;" :: "r"(dst), "l"(src))
#define CP_ASYNC16_Z(dst, src, sz) \
    asm volatile("cp.async.cg.shared.global [%0], [%1], 16, %2;" :: "r"(dst), "l"(src), "r"(sz))
#define CP_COMMIT()  asm volatile("cp.async.commit_group;" ::: "memory")
#define CP_WAIT1()   asm volatile("cp.async.wait_group 1;" ::: "memory")
#define LDMATRIX_X4(r0, r1, r2, r3, addr) \
    asm volatile("ldmatrix.sync.aligned.m8n8.x4.shared.b16 {%0,%1,%2,%3}, [%4];" \
        : "=r"(r0), "=r"(r1), "=r"(r2), "=r"(r3) : "r"(addr))

__device__ __forceinline__ void mma_tf32(float* acc, const uint32_t* a, const uint32_t* b) {
    asm volatile(
        "mma.sync.aligned.m16n8k8.row.col.f32.tf32.tf32.f32 "
        "{%0,%1,%2,%3}, {%4,%5,%6,%7}, {%8,%9}, {%0,%1,%2,%3};"
        : "+f"(acc[0]), "+f"(acc[1]), "+f"(acc[2]), "+f"(acc[3])
        : "r"(a[0]), "r"(a[1]), "r"(a[2]), "r"(a[3]), "r"(b[0]), "r"(b[1]));
}

// ---------------- kernel ----------------
// PERSISTENT version of the best kernel (R10): 444 CTAs (3/SM) loop over the
// 1926 (channel, p-tile) tiles; the cp.async ring keeps rolling ACROSS tile
// boundaries (prefetch of tile w+1 overlaps epilogue of tile w), removing the
// per-wave pipeline fill/drain that a 4.34-wave launch pays 5 times.
// Per-tile math identical to R10: M=64 x N=128 x K=512 tf32 mma.sync,
// 8 warps 1x8 (warp tile 64x16), A via 3-stage cp.async + ldmatrix (x truncated),
// B via padded smem LDS (W rounded).
__global__ void __launch_bounds__(NTHREADS, 3)
pc_linear_persist(const float* __restrict__ x,
                  const float* __restrict__ W,
                  const float* __restrict__ bias,
                  float* __restrict__ out)
{
    extern __shared__ float sm[];
    const uint32_t sbase = smem_to_u32(sm);

    const int tid  = threadIdx.x;
    const int lane = tid & 31;
    const int wid  = tid >> 5;    // warp col (0..7) -> n0 = wid*16
    const int gid  = lane >> 2;   // fragment group id (0..7)
    const int tig  = lane & 3;    // thread in group (0..3)
    const int bid  = blockIdx.x;

    // ---- per-lane ldmatrix offsets (A tile; mt adds 2048B = 16 rows) ----
    uint32_t foff[4];
    {
        const int m0  = (lane & 7) + (lane & 8);
        const int swz = (m0 & 7) * 16;
        const int hi  = (lane >> 4) * 16;
#pragma unroll
        for (int ks = 0; ks < 4; ++ks)
            foff[ks] = (uint32_t)(m0 * 128 + ((ks * 32 + hi) ^ swz));
    }

    // hoisted per-thread issue addressing (constant offsets within a tile)
    const int arA   = tid >> 3;           // A: batch row (two ops: +0, +256 threads)
    const int acol0 = (tid & 7) * 4;
    const uint32_t afo0 = (uint32_t)(arA * 32 + (acol0 ^ ((arA & 7) * 4)));
    const int arA1   = (tid + NTHREADS) >> 3;
    const int acol1  = ((tid + NTHREADS) & 7) * 4;
    const uint32_t afo1 = (uint32_t)(arA1 * 32 + (acol1 ^ ((arA1 & 7) * 4)));

    // ---- cp.async issue for global chunk index Lp (maps to tile, k-chunk) ----
    auto issue = [&](int Lp) {
        const int wp   = Lp >> 4;               // which of my tiles
        const int tile = bid + wp * NSLOTS;
        if (tile >= NTILES) return;             // tail: nothing to load
        const int cc = tile / 6;
        const int px = tile - cc * 6;
        const int k0 = (Lp & 15) * BK;
        const int p0 = px * BN;
        const int stage = Lp % STAGES;

        const float* xc = x + (size_t)cc * D_K;
        const float* Wc = W + (size_t)cc * ((size_t)D_K * P_OUT);

        // A tile: 64 rows x 32 floats, 16B-chunk swizzle
        const uint32_t abase = sbase + (uint32_t)stage * A_STAGE_BYTES;
        CP_ASYNC16(abase + afo0 * 4, xc + (size_t)arA  * (C_CH * D_K) + k0 + acol0);
        CP_ASYNC16(abase + afo1 * 4, xc + (size_t)arA1 * (C_CH * D_K) + k0 + acol1);

        // B tile: 32 rows x 128 floats (pad 136); zero-fill OOB p
        const uint32_t bbase = sbase + B_BASE + (uint32_t)stage * B_STAGE_BYTES;
#pragma unroll
        for (int j = 0; j < 4; ++j) {
            const int id  = tid + j * NTHREADS;
            const int r   = id >> 5;
            const int col = (id & 31) * 4;
            const float* src = Wc + (size_t)(k0 + r) * P_OUT + p0 + col;
            const int sz = (p0 + col < P_OUT) ? 16 : 0;
            CP_ASYNC16_Z(bbase + (uint32_t)(r * B_STRIDE + col) * 4, src, sz);
        }
    };

    float acc[4][2][4];   // mt x nt x quad
#pragma unroll
    for (int mt = 0; mt < 4; ++mt)
#pragma unroll
        for (int nt = 0; nt < 2; ++nt)
#pragma unroll
            for (int q = 0; q < 4; ++q) acc[mt][nt][q] = 0.f;

    // ---- prologue: 2 chunks in flight ----
    issue(0); CP_COMMIT();
    issue(1); CP_COMMIT();

    // ---- persistent loop over my tiles; chunk counter L runs continuously ----
    int L = 0;
#pragma unroll 1
    for (int w = 0; ; ++w) {
        const int tile = bid + w * NSLOTS;
        if (tile >= NTILES) break;
        const int cc = tile / 6;
        const int px = tile - cc * 6;
        const int p0 = px * BN;

#pragma unroll 1
        for (int i = 0; i < KCHUNKS; ++i, ++L) {
            CP_WAIT1();              // chunk L landed (2 + L commits so far)
            __syncthreads();         // publish stage; proves compute(L-1) done
            issue(L + 2);            // may belong to the NEXT tile (ring rolls on)
            CP_COMMIT();             // commit every iter keeps ledger exact

            const int s = L % STAGES;
            const uint32_t As_b = sbase + (uint32_t)s * A_STAGE_BYTES;
            const float*   Bs   = sm + (B_BASE / 4) + (size_t)s * (B_STAGE_BYTES / 4);

#pragma unroll
            for (int ks = 0; ks < 4; ++ks) {
                uint32_t af[4][4], bf[2][2];
                const uint32_t a0 = As_b + foff[ks];
#pragma unroll
                for (int mt = 0; mt < 4; ++mt)
                    LDMATRIX_X4(af[mt][0], af[mt][1], af[mt][2], af[mt][3],
                                a0 + (uint32_t)mt * 2048);

                const int kb = ks * 8 + tig;
#pragma unroll
                for (int nt = 0; nt < 2; ++nt) {
                    const int col = wid * 16 + nt * 8 + gid;
                    bf[nt][0] = rtf32(Bs[kb * B_STRIDE + col]);
                    bf[nt][1] = rtf32(Bs[(kb + 4) * B_STRIDE + col]);
                }
#pragma unroll
                for (int mt = 0; mt < 4; ++mt)
#pragma unroll
                    for (int nt = 0; nt < 2; ++nt)
                        mma_tf32(acc[mt][nt], af[mt], bf[nt]);
            }
        }

        // ---- tile epilogue (overlaps with already-issued prefetches) ----
#pragma unroll
        for (int nt = 0; nt < 2; ++nt) {
            const int p = p0 + wid * 16 + nt * 8 + tig * 2;
            if (p < P_OUT) {
                const float2 bv = *(const float2*)(bias + (size_t)cc * P_OUT + p);
#pragma unroll
                for (int mt = 0; mt < 4; ++mt) {
                    const int b0r = mt * 16 + gid;
                    const float* a = acc[mt][nt];
                    float2 v0 = make_float2(a[0] + bv.x, a[1] + bv.y);
                    float2 v1 = make_float2(a[2] + bv.x, a[3] + bv.y);
                    *(float2*)(out + ((size_t)b0r * C_CH + cc) * P_OUT + p)       = v0;
                    *(float2*)(out + ((size_t)(b0r + 8) * C_CH + cc) * P_OUT + p) = v1;
                }
            }
        }
#pragma unroll
        for (int mt = 0; mt < 4; ++mt)
#pragma unroll
            for (int nt = 0; nt < 2; ++nt)
#pragma unroll
                for (int q = 0; q < 4; ++q) acc[mt][nt][q] = 0.f;
    }
}

// ---------------- launch ----------------
extern "C" void kernel_launch(void* const* d_in, const int* in_sizes, int n_in,
                              void* d_out, int out_size) {
    const float* x  = (const float*)d_in[0];  // [64, 321, 512]
    const float* W  = (const float*)d_in[1];  // [321, 512, 720]
    const float* bi = (const float*)d_in[2];  // [321, 720]
    float* out      = (float*)d_out;          // [64, 321, 720]

    cudaFuncSetAttribute(pc_linear_persist,
                         cudaFuncAttributeMaxDynamicSharedMemorySize, SMEM_BYTES);
    pc_linear_persist<<<NSLOTS, NTHREADS, SMEM_BYTES>>>(x, W, bi, out);
}